// round 11
// baseline (speedup 1.0000x reference)
#include <cuda_runtime.h>
#include <cuda_bf16.h>
#include <math.h>
#include <stdint.h>

// ---------------------------------------------------------------------------
// BagAttentionNet forward.
//   h-chain (512->256->256->128, relu) on mma.sync bf16 (HMMA) with
//   3-split/6-product exact-fp32 emulation. Warp-specialized: 8 consumer
//   warps (MMA) + 4 producer warps (cp.async + fp32->3xbf16 convert), named
//   barriers. fp32 in / fp32 out. D-chain + tail: SIMT fp32 (FFMA2).
// ---------------------------------------------------------------------------

#define NB 2048
#define CI 64
#define MR (NB * CI)          // 131072
#define TAU_F 0.95f

typedef unsigned long long ull;

// ---------------- scratch (__device__ globals; no allocs allowed) ----------
__device__ float g_h1f[(size_t)MR * 256];
__device__ float g_h2f[(size_t)MR * 256];
__device__ float g_h3 [(size_t)MR * 128];
__device__ float g_d1 [(size_t)MR * 128];
__device__ float g_d2 [(size_t)MR * 64];
__device__ float g_dd [MR];
__device__ __nv_bfloat16 g_w1t[3 * 512 * 256];     // W1^T planes [3][256][512]
__device__ __nv_bfloat16 g_w2t[3 * 256 * 256];     // W2^T planes [3][256][256]
__device__ __nv_bfloat16 g_w3t[3 * 256 * 128];     // W3^T planes [3][128][256]

// ---------------- helpers ----------------------------------------------------
__device__ __forceinline__ void cp_async16(void* s, const void* g) {
    unsigned sa = (unsigned)__cvta_generic_to_shared(s);
    asm volatile("cp.async.cg.shared.global [%0], [%1], 16;" :: "r"(sa), "l"(g));
}
#define CP_COMMIT() asm volatile("cp.async.commit_group;")
#define BAR_SYNC(id)   asm volatile("bar.sync %0, 384;"   :: "r"(id) : "memory")
#define BAR_ARRIVE(id) asm volatile("bar.arrive %0, 384;" :: "r"(id) : "memory")

__device__ __forceinline__ void split3(float v, __nv_bfloat16& h,
                                       __nv_bfloat16& m, __nv_bfloat16& l) {
    h = __float2bfloat16(v);  float q = v - __bfloat162float(h);
    m = __float2bfloat16(q);  float s = q - __bfloat162float(m);
    l = __float2bfloat16(s);
}

__device__ __forceinline__ void ldsm_x4(uint32_t& r0, uint32_t& r1,
                                        uint32_t& r2, uint32_t& r3, uint32_t addr) {
    asm volatile("ldmatrix.sync.aligned.m8n8.x4.shared.b16 {%0,%1,%2,%3},[%4];"
        : "=r"(r0), "=r"(r1), "=r"(r2), "=r"(r3) : "r"(addr));
}

__device__ __forceinline__ void hmma16816(float* c, const uint32_t* a, const uint32_t* b) {
    asm volatile("mma.sync.aligned.m16n8k16.row.col.f32.bf16.bf16.f32 "
        "{%0,%1,%2,%3},{%4,%5,%6,%7},{%8,%9},{%0,%1,%2,%3};"
        : "+f"(c[0]), "+f"(c[1]), "+f"(c[2]), "+f"(c[3])
        : "r"(a[0]), "r"(a[1]), "r"(a[2]), "r"(a[3]), "r"(b[0]), "r"(b[1]));
}

// W[K][N] -> planes [3][N][K] (transpose + split)
__global__ void split_wt_kernel(const float* __restrict__ W,
                                __nv_bfloat16* __restrict__ o, int K, int N) {
    int idx = blockIdx.x * blockDim.x + threadIdx.x;
    if (idx >= K * N) return;
    int k = idx / N, n = idx % N;
    __nv_bfloat16 h, m, l;
    split3(W[idx], h, m, l);
    size_t pl = (size_t)K * N;
    size_t off = (size_t)n * K + k;
    o[off] = h; o[pl + off] = m; o[2 * pl + off] = l;
}

// ---------------- warp-specialized HMMA split GEMM ---------------------------
// A: fp32 [M][K]. B: 3 bf16 planes [3][ldN][K] (=W^T). Out: fp32 relu [M][ldN].
// Warps 0-7: consumers (MMA). Warps 8-11: producers (cp.async + convert).
// Named barriers: FULL[b] = 1+b (prod arrive -> cons sync),
//                 FREE[b] = 3+b (cons arrive -> prod sync).
#define TROW 80                            // 64B data + 16B pad
#define TILE_B (128 * TROW)                // 10240
#define APL_B (3 * TILE_B)                 // 30720
#define BPL_B (3 * TILE_B)                 // 30720
#define FST_B (128 * 144)                  // 18432 (fp32 tile, 36-float stride)
#define BUF_B (APL_B + BPL_B + FST_B)      // 79872
#define HSMEM2 (2 * BUF_B)                 // 159744

__global__ void __launch_bounds__(384, 1)
hmma_gemm(const float* __restrict__ Af, const __nv_bfloat16* __restrict__ Bp,
          const float* __restrict__ bias, float* __restrict__ Cout,
          int K, int ldN)
{
    extern __shared__ char smem[];
    __shared__ float sbias[128];
    const uint32_t sb = (uint32_t)__cvta_generic_to_shared(smem);
    const int tid = threadIdx.x, wid = tid >> 5, lane = tid & 31;
    const int brow = blockIdx.y * 128, bcol = blockIdx.x * 128;
    const size_t bplane = (size_t)ldN * K;
    const int NT = K / 32;

    if (tid < 128) sbias[tid] = bias[bcol + tid];
    __syncthreads();

    if (wid >= 8) {
        // ===================== PRODUCER (warps 8-11) =====================
        const int ptid = tid - 256;       // 0..127
        const char* Bg = (const char*)Bp;

        auto load_kt = [&](int kt, int b) {
            char* st = smem + b * BUF_B;
            // B planes: 1536 16B chunks, 12 per thread
#pragma unroll
            for (int i = 0; i < 12; i++) {
                int c = ptid + i * 128;
                int p = c >> 9, rem = c & 511;
                int row = rem >> 2, col4 = rem & 3;
                cp_async16(st + APL_B + p * TILE_B + row * TROW + col4 * 16,
                    Bg + ((size_t)p * bplane + (size_t)(bcol + row) * K) * 2
                       + (size_t)kt * 64 + col4 * 16);
            }
            // fp32 A tile: 1024 chunks, 8 per thread
            char* fs = st + APL_B + BPL_B;
#pragma unroll
            for (int i = 0; i < 8; i++) {
                int c = ptid + i * 128;
                int row = c >> 3, col = c & 7;
                cp_async16(fs + row * 144 + col * 16,
                    (const char*)(Af + (size_t)(brow + row) * K + kt * 32 + col * 4));
            }
        };
        auto convert_own = [&](int b) {
            const float* fs = (const float*)(smem + b * BUF_B + APL_B + BPL_B);
            char* ap = smem + b * BUF_B;
#pragma unroll
            for (int i = 0; i < 8; i++) {
                int c = ptid + i * 128;
                int row = c >> 3, col = c & 7;
                float4 v = *(const float4*)(fs + row * 36 + col * 4);
                float vv[4] = {v.x, v.y, v.z, v.w};
                __nv_bfloat16 h[4], mm[4], l[4];
#pragma unroll
                for (int e = 0; e < 4; e++) split3(vv[e], h[e], mm[e], l[e]);
                const uint32_t off = row * TROW + col * 8;
                *(__nv_bfloat162*)(ap + off)                  = __halves2bfloat162(h[0], h[1]);
                *(__nv_bfloat162*)(ap + off + 4)              = __halves2bfloat162(h[2], h[3]);
                *(__nv_bfloat162*)(ap + TILE_B + off)         = __halves2bfloat162(mm[0], mm[1]);
                *(__nv_bfloat162*)(ap + TILE_B + off + 4)     = __halves2bfloat162(mm[2], mm[3]);
                *(__nv_bfloat162*)(ap + 2 * TILE_B + off)     = __halves2bfloat162(l[0], l[1]);
                *(__nv_bfloat162*)(ap + 2 * TILE_B + off + 4) = __halves2bfloat162(l[2], l[3]);
            }
        };

        load_kt(0, 0); CP_COMMIT();
        load_kt(1, 1); CP_COMMIT();
        for (int kt = 0; kt < NT; kt++) {
            const int b = kt & 1;
            if (kt + 1 < NT) asm volatile("cp.async.wait_group 1;");
            else             asm volatile("cp.async.wait_group 0;");
            convert_own(kt & 1);
            asm volatile("membar.cta;" ::: "memory");
            BAR_ARRIVE(1 + b);                       // FULL[b]
            if (kt + 2 < NT) {
                BAR_SYNC(3 + b);                     // FREE[b]: MMA(kt) done
                load_kt(kt + 2, b); CP_COMMIT();
            }
        }
    } else {
        // ===================== CONSUMER (warps 0-7) ======================
        const int mbase = (wid >> 2) * 64;
        const int nbase = (wid & 3) * 32;
        const int a_r  = (lane & 15);
        const int a_kc = (lane & 16) ? 16 : 0;
        const int b_n  = (lane & 7) + ((lane & 16) ? 8 : 0);
        const int b_kc = (lane & 8) ? 16 : 0;

        float acc[4][4][4];
#pragma unroll
        for (int i = 0; i < 4; i++)
#pragma unroll
            for (int j = 0; j < 4; j++)
#pragma unroll
                for (int q = 0; q < 4; q++) acc[i][j][q] = 0.f;

        for (int kt = 0; kt < NT; kt++) {
            const int b = kt & 1;
            BAR_SYNC(1 + b);                         // FULL[b]
            const uint32_t stb = sb + b * BUF_B;
#pragma unroll
            for (int k16 = 0; k16 < 2; k16++) {
                const int kk = k16 * 32;
                uint32_t afr[4][4], bfr[4][2];
#pragma unroll
                for (int pa = 0; pa < 3; pa++) {
                    const uint32_t abase = stb + pa * TILE_B + kk + a_kc;
#pragma unroll
                    for (int mf = 0; mf < 4; mf++)
                        ldsm_x4(afr[mf][0], afr[mf][1], afr[mf][2], afr[mf][3],
                                abase + (mbase + mf * 16 + a_r) * TROW);
                    const int npb = (pa == 0) ? 3 : (pa == 1) ? 2 : 1;
#pragma unroll
                    for (int pb = 0; pb < 3; pb++) {
                        if (pb >= npb) break;
                        const uint32_t bbase = stb + APL_B + pb * TILE_B + kk + b_kc;
#pragma unroll
                        for (int nf2 = 0; nf2 < 2; nf2++) {
                            uint32_t r0, r1, r2, r3;
                            ldsm_x4(r0, r1, r2, r3,
                                    bbase + (nbase + nf2 * 16 + b_n) * TROW);
                            bfr[nf2 * 2 + 0][0] = r0; bfr[nf2 * 2 + 0][1] = r1;
                            bfr[nf2 * 2 + 1][0] = r2; bfr[nf2 * 2 + 1][1] = r3;
                        }
#pragma unroll
                        for (int mf = 0; mf < 4; mf++)
#pragma unroll
                            for (int nf = 0; nf < 4; nf++)
                                hmma16816(acc[mf][nf], afr[mf], bfr[nf]);
                    }
                }
            }
            if (kt + 2 < NT) BAR_ARRIVE(3 + b);      // FREE[b] (safe: after HMMAs)
        }

        // ---- epilogue: bias + relu -> fp32 ----
        const int qr = lane >> 2, qc = (lane & 3) * 2;
#pragma unroll
        for (int mf = 0; mf < 4; mf++) {
#pragma unroll
            for (int half = 0; half < 2; half++) {
                const int row = brow + mbase + mf * 16 + qr + half * 8;
#pragma unroll
                for (int nf = 0; nf < 4; nf++) {
                    const int colL = nbase + nf * 8 + qc;
                    float v0 = fmaxf(acc[mf][nf][half * 2 + 0] + sbias[colL],     0.f);
                    float v1 = fmaxf(acc[mf][nf][half * 2 + 1] + sbias[colL + 1], 0.f);
                    *(float2*)(Cout + (size_t)row * ldN + bcol + colL) = make_float2(v0, v1);
                }
            }
        }
    }
}

// ---------------- SIMT FFMA2 GEMM (D-chain) ----------------------------------
__device__ __forceinline__ float act_apply(float v, int ACT) {
    if (ACT == 1) return v > 0.f ? v : 0.f;
    if (ACT == 2) return __fdividef(1.f, 1.f + __expf(-v));
    return v;
}

template<int BM, int BN, int BK, int ACT>
__global__ void __launch_bounds__((BM / 16) * (BN / 4), 2)
gemm2(const float* __restrict__ A, const float* __restrict__ W,
      const float* __restrict__ bias, float* __restrict__ Cmat,
      int K, int N)
{
    constexpr int TN = 4;
    constexpr int RX = BN / TN, RY = BM / 16, THREADS = RX * RY;
    constexpr int GROUPS = THREADS / BM;
    constexpr int KC  = BK / GROUPS;
    constexpr int AF4 = KC / 4;
    constexpr int WC  = (BK * BN) / (4 * THREADS);
    constexpr int BMP = BM + 4;
    constexpr int N4  = BN / 4;

    extern __shared__ float smemf[];
    float (*As)[BK][BMP] = (float (*)[BK][BMP])smemf;
    float (*Ws)[BK][BN]  = (float (*)[BK][BN])(smemf + 2 * BK * BMP);

    const int tid  = threadIdx.x;
    const int tcol = tid % RX;
    const int trow = tid / RX;
    const int brow = blockIdx.y * BM;
    const int bcol = blockIdx.x * BN;

    const int arow = tid % BM;
    const int akb  = (tid / BM) * KC;
    const float* Arow = A + (size_t)(brow + arow) * K + akb;

    ull acc2[8][TN];
#pragma unroll
    for (int i = 0; i < 8; i++)
#pragma unroll
        for (int j = 0; j < TN; j++) acc2[i][j] = 0ull;

    float4 areg[AF4];
    const int nt = K / BK;

#pragma unroll
    for (int q = 0; q < AF4; q++) areg[q] = *(const float4*)(Arow + q * 4);
#pragma unroll
    for (int i = 0; i < WC; i++) {
        int idx = tid + i * THREADS;
        int k = idx / N4, n4 = idx % N4;
        cp_async16(&Ws[0][k][n4 * 4], W + (size_t)k * N + bcol + n4 * 4);
    }
    CP_COMMIT();
#pragma unroll
    for (int q = 0; q < AF4; q++) {
        As[0][akb + q * 4 + 0][arow] = areg[q].x;
        As[0][akb + q * 4 + 1][arow] = areg[q].y;
        As[0][akb + q * 4 + 2][arow] = areg[q].z;
        As[0][akb + q * 4 + 3][arow] = areg[q].w;
    }
    asm volatile("cp.async.wait_group 0;");
    __syncthreads();

    for (int t = 0; t < nt; t++) {
        const int cb = t & 1;
        const bool more = (t + 1 < nt);
        if (more) {
            const float* Ap2 = Arow + (size_t)(t + 1) * BK;
#pragma unroll
            for (int q = 0; q < AF4; q++) areg[q] = *(const float4*)(Ap2 + q * 4);
            const float* Wp = W + (size_t)(t + 1) * BK * N + bcol;
#pragma unroll
            for (int i = 0; i < WC; i++) {
                int idx = tid + i * THREADS;
                int k = idx / N4, n4 = idx % N4;
                cp_async16(&Ws[cb ^ 1][k][n4 * 4], Wp + (size_t)k * N + n4 * 4);
            }
            CP_COMMIT();
        }
#pragma unroll
        for (int k = 0; k < BK; k++) {
            float4 wv = *(const float4*)&Ws[cb][k][tcol * 4];
            ull wb0, wb1, wb2, wb3;
            asm("mov.b64 %0, {%1, %1};" : "=l"(wb0) : "f"(wv.x));
            asm("mov.b64 %0, {%1, %1};" : "=l"(wb1) : "f"(wv.y));
            asm("mov.b64 %0, {%1, %1};" : "=l"(wb2) : "f"(wv.z));
            asm("mov.b64 %0, {%1, %1};" : "=l"(wb3) : "f"(wv.w));
            const float* ab = &As[cb][k][trow * 16];
            ulonglong2 p01 = *(const ulonglong2*)(ab + 0);
            ulonglong2 p23 = *(const ulonglong2*)(ab + 4);
            ulonglong2 p45 = *(const ulonglong2*)(ab + 8);
            ulonglong2 p67 = *(const ulonglong2*)(ab + 12);
            ull ap[8] = {p01.x, p01.y, p23.x, p23.y, p45.x, p45.y, p67.x, p67.y};
#pragma unroll
            for (int i = 0; i < 8; i++) {
                asm("fma.rn.f32x2 %0, %1, %2, %0;" : "+l"(acc2[i][0]) : "l"(ap[i]), "l"(wb0));
                asm("fma.rn.f32x2 %0, %1, %2, %0;" : "+l"(acc2[i][1]) : "l"(ap[i]), "l"(wb1));
                asm("fma.rn.f32x2 %0, %1, %2, %0;" : "+l"(acc2[i][2]) : "l"(ap[i]), "l"(wb2));
                asm("fma.rn.f32x2 %0, %1, %2, %0;" : "+l"(acc2[i][3]) : "l"(ap[i]), "l"(wb3));
            }
        }
        if (more) {
#pragma unroll
            for (int q = 0; q < AF4; q++) {
                As[cb ^ 1][akb + q * 4 + 0][arow] = areg[q].x;
                As[cb ^ 1][akb + q * 4 + 1][arow] = areg[q].y;
                As[cb ^ 1][akb + q * 4 + 2][arow] = areg[q].z;
                As[cb ^ 1][akb + q * 4 + 3][arow] = areg[q].w;
            }
            asm volatile("cp.async.wait_group 0;");
        }
        __syncthreads();
    }

    const int colb = bcol + tcol * 4;
    float4 bv = *(const float4*)(bias + colb);
#pragma unroll
    for (int i2 = 0; i2 < 8; i2++) {
        int row0 = brow + trow * 16 + 2 * i2;
        float e0, o0, e1, o1, e2, o2, e3, o3;
        asm("mov.b64 {%0, %1}, %2;" : "=f"(e0), "=f"(o0) : "l"(acc2[i2][0]));
        asm("mov.b64 {%0, %1}, %2;" : "=f"(e1), "=f"(o1) : "l"(acc2[i2][1]));
        asm("mov.b64 {%0, %1}, %2;" : "=f"(e2), "=f"(o2) : "l"(acc2[i2][2]));
        asm("mov.b64 {%0, %1}, %2;" : "=f"(e3), "=f"(o3) : "l"(acc2[i2][3]));
        float4 re, ro;
        re.x = act_apply(e0 + bv.x, ACT); re.y = act_apply(e1 + bv.y, ACT);
        re.z = act_apply(e2 + bv.z, ACT); re.w = act_apply(e3 + bv.w, ACT);
        ro.x = act_apply(o0 + bv.x, ACT); ro.y = act_apply(o1 + bv.y, ACT);
        ro.z = act_apply(o2 + bv.z, ACT); ro.w = act_apply(o3 + bv.w, ACT);
        *(float4*)(Cmat + (size_t)row0 * N + colb)       = re;
        *(float4*)(Cmat + (size_t)(row0 + 1) * N + colb) = ro;
    }
}

// d[r] = d2[r,:] . D3 + db3   (K = 64)
__global__ void dot_kernel(const float* __restrict__ d2, const float* __restrict__ D3,
                           const float* __restrict__ db3, float* __restrict__ dd)
{
    int gw   = (blockIdx.x * blockDim.x + threadIdx.x) >> 5;
    int lane = threadIdx.x & 31;
    if (gw >= MR) return;
    const float* row = d2 + (size_t)gw * 64;
    float s = row[lane] * D3[lane] + row[lane + 32] * D3[lane + 32];
#pragma unroll
    for (int o = 16; o > 0; o >>= 1) s += __shfl_down_sync(0xffffffffu, s, o);
    if (lane == 0) dd[gw] = s + db3[0];
}

// Per-bag: gumbel softmax, top-20 keep (stable), re-softmax, aggregate, project.
__global__ void __launch_bounds__(128)
final_kernel(const float* __restrict__ dd, const float* __restrict__ m,
             const float* __restrict__ u, const float* __restrict__ h3,
             const float* __restrict__ E, const float* __restrict__ eb,
             float* __restrict__ out_w, float* __restrict__ out_s)
{
    const int bag = blockIdx.x;
    const int t   = threadIdx.x;

    __shared__ float sm[64];
    __shared__ float wf[64];
    __shared__ float red[128];

    float z = 0.f;
    if (t < 64) {
        float logit = m[bag * 64 + t] * dd[bag * 64 + t];
        float uu = u[bag * 64 + t];
        float g = -logf(-logf(uu));
        z = (logit + g) / TAU_F;
    }

    red[t] = (t < 64) ? z : -INFINITY;
    __syncthreads();
#pragma unroll
    for (int s = 64; s >= 1; s >>= 1) {
        if (t < s) red[t] = fmaxf(red[t], red[t + s]);
        __syncthreads();
    }
    float zmax = red[0];
    __syncthreads();

    float e = (t < 64) ? expf(z - zmax) : 0.f;
    red[t] = e;
    __syncthreads();
#pragma unroll
    for (int s = 64; s >= 1; s >>= 1) {
        if (t < s) red[t] += red[t + s];
        __syncthreads();
    }
    float psum = red[0];
    __syncthreads();

    float p = e / psum;
    if (t < 64) sm[t] = p;
    __syncthreads();

    int keep = 0;
    if (t < 64) {
        int pos = 0;
#pragma unroll 8
        for (int j = 0; j < 64; j++) {
            float o = sm[j];
            pos += (o < p) || (o == p && j < t);
        }
        keep = (pos >= 44);
    }

    red[t] = (t < 64 && keep) ? p : -INFINITY;
    __syncthreads();
#pragma unroll
    for (int s = 64; s >= 1; s >>= 1) {
        if (t < s) red[t] = fmaxf(red[t], red[t + s]);
        __syncthreads();
    }
    float m2 = red[0];
    __syncthreads();

    float e2 = (t < 64 && keep) ? expf(p - m2) : 0.f;
    red[t] = e2;
    __syncthreads();
#pragma unroll
    for (int s = 64; s >= 1; s >>= 1) {
        if (t < s) red[t] += red[t + s];
        __syncthreads();
    }
    float s2 = red[0];
    __syncthreads();

    float wfin = (t < 64 && keep) ? (e2 / s2) : 0.f;
    if (t < 64) {
        wf[t] = wfin;
        out_w[bag * 64 + t] = wfin;
    }
    __syncthreads();

    const float* hb = h3 + (size_t)bag * 64 * 128;
    float agg = 0.f;
#pragma unroll 8
    for (int c = 0; c < 64; c++) agg += wf[c] * hb[c * 128 + t];
    red[t] = agg * E[t];
    __syncthreads();
#pragma unroll
    for (int s = 64; s >= 1; s >>= 1) {
        if (t < s) red[t] += red[t + s];
        __syncthreads();
    }
    if (t == 0) out_s[bag] = red[0] + eb[0];
}

// ---------------- launch ------------------------------------------------------
extern "C" void kernel_launch(void* const* d_in, const int* in_sizes, int n_in,
                              void* d_out, int out_size)
{
    const float* x   = (const float*)d_in[0];
    const float* m   = (const float*)d_in[1];
    const float* u   = (const float*)d_in[2];
    const float* W1  = (const float*)d_in[3];
    const float* b1  = (const float*)d_in[4];
    const float* W2  = (const float*)d_in[5];
    const float* b2  = (const float*)d_in[6];
    const float* W3  = (const float*)d_in[7];
    const float* b3  = (const float*)d_in[8];
    const float* D1  = (const float*)d_in[9];
    const float* db1 = (const float*)d_in[10];
    const float* D2  = (const float*)d_in[11];
    const float* db2 = (const float*)d_in[12];
    const float* D3  = (const float*)d_in[13];
    const float* db3 = (const float*)d_in[14];
    const float* E   = (const float*)d_in[15];
    const float* eb  = (const float*)d_in[16];
    float* out = (float*)d_out;

    __nv_bfloat16 *w1t, *w2t, *w3t;
    float *h1f, *h2f, *h3, *d1, *d2, *dd;
    cudaGetSymbolAddress((void**)&w1t, g_w1t);
    cudaGetSymbolAddress((void**)&w2t, g_w2t);
    cudaGetSymbolAddress((void**)&w3t, g_w3t);
    cudaGetSymbolAddress((void**)&h1f, g_h1f);
    cudaGetSymbolAddress((void**)&h2f, g_h2f);
    cudaGetSymbolAddress((void**)&h3,  g_h3);
    cudaGetSymbolAddress((void**)&d1,  g_d1);
    cudaGetSymbolAddress((void**)&d2,  g_d2);
    cudaGetSymbolAddress((void**)&dd,  g_dd);

    constexpr int S128 = (2 * 32 * 132 + 2 * 32 * 128) * 4;
    constexpr int S64  = (2 * 16 * 132 + 2 * 16 * 64) * 4;

    static int attr_done = 0;
    if (!attr_done) {
        cudaFuncSetAttribute(hmma_gemm, cudaFuncAttributeMaxDynamicSharedMemorySize, HSMEM2);
        cudaFuncSetAttribute(gemm2<128,128,32,2>, cudaFuncAttributeMaxDynamicSharedMemorySize, S128);
        cudaFuncSetAttribute(gemm2<128, 64,16,2>, cudaFuncAttributeMaxDynamicSharedMemorySize, S64);
        attr_done = 1;
    }

    // weight splits (tiny)
    split_wt_kernel<<<(512 * 256 + 255) / 256, 256>>>(W1, w1t, 512, 256);
    split_wt_kernel<<<(256 * 256 + 255) / 256, 256>>>(W2, w2t, 256, 256);
    split_wt_kernel<<<(256 * 128 + 255) / 256, 256>>>(W3, w3t, 256, 128);

    // h-chain on HMMA (exact-fp32 via 3-split/6-product), warp-specialized
    hmma_gemm<<<dim3(2, MR / 128), 384, HSMEM2>>>(x,   w1t, b1, h1f, 512, 256);
    hmma_gemm<<<dim3(2, MR / 128), 384, HSMEM2>>>(h1f, w2t, b2, h2f, 256, 256);
    hmma_gemm<<<dim3(1, MR / 128), 384, HSMEM2>>>(h2f, w3t, b3, h3,  256, 128);

    // D-chain (SIMT FFMA2)
    gemm2<128,128,32,2><<<dim3(1, MR / 128), 256, S128>>>(h3, D1, db1, d1, 128, 128);
    gemm2<128, 64,16,2><<<dim3(1, MR / 128), 128, S64>>>(d1, D2, db2, d2, 128, 64);
    dot_kernel<<<MR / 8, 256>>>(d2, D3, db3, dd);
    final_kernel<<<NB, 128>>>(dd, m, u, h3, E, eb, out, out + MR);
}

// round 12
// speedup vs baseline: 1.1813x; 1.1813x over previous
#include <cuda_runtime.h>
#include <cuda_bf16.h>
#include <math.h>
#include <stdint.h>

// ---------------------------------------------------------------------------
// BagAttentionNet forward.
//   h-chain (512->256->256->128, relu) on mma.sync bf16 (HMMA) with
//   3-split/6-product exact-fp32 emulation. BN=256 CTA tiles: A loaded once
//   per row-block. fp32 in / in-kernel split / fp32 out. D-chain: SIMT FFMA2.
// ---------------------------------------------------------------------------

#define NB 2048
#define CI 64
#define MR (NB * CI)          // 131072
#define TAU_F 0.95f

typedef unsigned long long ull;

// ---------------- scratch (__device__ globals; no allocs allowed) ----------
__device__ float g_h1f[(size_t)MR * 256];
__device__ float g_h2f[(size_t)MR * 256];
__device__ float g_h3 [(size_t)MR * 128];
__device__ float g_d1 [(size_t)MR * 128];
__device__ float g_d2 [(size_t)MR * 64];
__device__ float g_dd [MR];
__device__ __nv_bfloat16 g_w1t[3 * 512 * 256];     // W1^T planes [3][256][512]
__device__ __nv_bfloat16 g_w2t[3 * 256 * 256];     // W2^T planes [3][256][256]
__device__ __nv_bfloat16 g_w3t[3 * 256 * 128];     // W3^T planes [3][128][256]

// ---------------- helpers ----------------------------------------------------
__device__ __forceinline__ void cp_async16(void* s, const void* g) {
    unsigned sa = (unsigned)__cvta_generic_to_shared(s);
    asm volatile("cp.async.cg.shared.global [%0], [%1], 16;" :: "r"(sa), "l"(g));
}
#define CP_COMMIT() asm volatile("cp.async.commit_group;")

__device__ __forceinline__ void split3(float v, __nv_bfloat16& h,
                                       __nv_bfloat16& m, __nv_bfloat16& l) {
    h = __float2bfloat16(v);  float q = v - __bfloat162float(h);
    m = __float2bfloat16(q);  float s = q - __bfloat162float(m);
    l = __float2bfloat16(s);
}

__device__ __forceinline__ void ldsm_x4(uint32_t& r0, uint32_t& r1,
                                        uint32_t& r2, uint32_t& r3, uint32_t addr) {
    asm volatile("ldmatrix.sync.aligned.m8n8.x4.shared.b16 {%0,%1,%2,%3},[%4];"
        : "=r"(r0), "=r"(r1), "=r"(r2), "=r"(r3) : "r"(addr));
}

__device__ __forceinline__ void hmma16816(float* c, const uint32_t* a, const uint32_t* b) {
    asm volatile("mma.sync.aligned.m16n8k16.row.col.f32.bf16.bf16.f32 "
        "{%0,%1,%2,%3},{%4,%5,%6,%7},{%8,%9},{%0,%1,%2,%3};"
        : "+f"(c[0]), "+f"(c[1]), "+f"(c[2]), "+f"(c[3])
        : "r"(a[0]), "r"(a[1]), "r"(a[2]), "r"(a[3]), "r"(b[0]), "r"(b[1]));
}

// W[K][N] -> planes [3][N][K] (transpose + split)
__global__ void split_wt_kernel(const float* __restrict__ W,
                                __nv_bfloat16* __restrict__ o, int K, int N) {
    int idx = blockIdx.x * blockDim.x + threadIdx.x;
    if (idx >= K * N) return;
    int k = idx / N, n = idx % N;
    __nv_bfloat16 h, m, l;
    split3(W[idx], h, m, l);
    size_t pl = (size_t)K * N;
    size_t off = (size_t)n * K + k;
    o[off] = h; o[pl + off] = m; o[2 * pl + off] = l;
}

// ---------------- HMMA split GEMM (BN-wide CTA tile) -------------------------
// A: fp32 [M][K]. B: 3 bf16 planes [3][ldN][K] (=W^T). Out: fp32 relu [M][ldN].
// CTA tile 128 x BN; warp tile 64 x (BN/4). In-kernel A split; R8 sync flow.
#define TROW 80                            // 64B data + 16B pad
#define TILE_A_B (128 * TROW)              // 10240 (one A plane tile)
#define APL_B (3 * TILE_A_B)               // 30720
#define FST_B (128 * 144)                  // 18432 (fp32 stage, 36-float stride)

template<int BN>
__global__ void __launch_bounds__(256, 1)
hmma_gemm(const float* __restrict__ Af, const __nv_bfloat16* __restrict__ Bp,
          const float* __restrict__ bias, float* __restrict__ Cout,
          int K, int ldN)
{
    constexpr int TILE_BB = BN * TROW;         // one B plane tile bytes
    constexpr int BPL = 3 * TILE_BB;
    constexpr int BUF = APL_B + BPL + FST_B;
    constexpr int NF = BN / 32;                // n-fragments per warp (8 or 4)
    constexpr int NB_IT = (12 * BN) / 256;     // B chunks per thread

    extern __shared__ char smem[];
    __shared__ float sbias[BN];
    const uint32_t sb = (uint32_t)__cvta_generic_to_shared(smem);
    const int tid = threadIdx.x, wid = tid >> 5, lane = tid & 31;
    const int brow = blockIdx.y * 128, bcol = blockIdx.x * BN;
    const int mbase = (wid >> 2) * 64;
    const int nbase = (wid & 3) * (BN / 4);
    const size_t bplane = (size_t)ldN * K;
    const int NT = K / 32;

    if (tid < BN) sbias[tid] = bias[bcol + tid];

    const char* Bg = (const char*)Bp;

    auto load_kt = [&](int kt, int b) {
        char* st = smem + b * BUF;
        // B planes: 12*BN chunks
#pragma unroll
        for (int i = 0; i < NB_IT; i++) {
            int c = tid + i * 256;
            int p = c / (BN * 4), rem = c % (BN * 4);
            int row = rem >> 2, col4 = rem & 3;
            cp_async16(st + APL_B + p * TILE_BB + row * TROW + col4 * 16,
                Bg + ((size_t)p * bplane + (size_t)(bcol + row) * K) * 2
                   + (size_t)kt * 64 + col4 * 16);
        }
        // fp32 A tile: 1024 chunks, 4 per thread
        char* fs = st + APL_B + BPL;
#pragma unroll
        for (int i = 0; i < 4; i++) {
            int c = tid + i * 256;
            int row = c >> 3, col = c & 7;
            cp_async16(fs + row * 144 + col * 16,
                (const char*)(Af + (size_t)(brow + row) * K + kt * 32 + col * 4));
        }
    };

    auto convert_own = [&](int b) {
        const float* fs = (const float*)(smem + b * BUF + APL_B + BPL);
        char* ap = smem + b * BUF;
#pragma unroll
        for (int i = 0; i < 4; i++) {
            int c = tid + i * 256;
            int row = c >> 3, col = c & 7;
            float4 v = *(const float4*)(fs + row * 36 + col * 4);
            float vv[4] = {v.x, v.y, v.z, v.w};
            __nv_bfloat16 h[4], mm[4], l[4];
#pragma unroll
            for (int e = 0; e < 4; e++) split3(vv[e], h[e], mm[e], l[e]);
            const uint32_t off = row * TROW + col * 8;
            *(__nv_bfloat162*)(ap + off)                      = __halves2bfloat162(h[0], h[1]);
            *(__nv_bfloat162*)(ap + off + 4)                  = __halves2bfloat162(h[2], h[3]);
            *(__nv_bfloat162*)(ap + TILE_A_B + off)           = __halves2bfloat162(mm[0], mm[1]);
            *(__nv_bfloat162*)(ap + TILE_A_B + off + 4)       = __halves2bfloat162(mm[2], mm[3]);
            *(__nv_bfloat162*)(ap + 2 * TILE_A_B + off)       = __halves2bfloat162(l[0], l[1]);
            *(__nv_bfloat162*)(ap + 2 * TILE_A_B + off + 4)   = __halves2bfloat162(l[2], l[3]);
        }
    };

    float acc[4][NF][4];
#pragma unroll
    for (int i = 0; i < 4; i++)
#pragma unroll
        for (int j = 0; j < NF; j++)
#pragma unroll
            for (int q = 0; q < 4; q++) acc[i][j][q] = 0.f;

    load_kt(0, 0); CP_COMMIT();
    load_kt(1, 1); CP_COMMIT();
    asm volatile("cp.async.wait_group 1;");
    convert_own(0);

    const int a_r  = (lane & 15);
    const int a_kc = (lane & 16) ? 16 : 0;
    const int b_n  = (lane & 7) + ((lane & 16) ? 8 : 0);
    const int b_kc = (lane & 8) ? 16 : 0;

    for (int kt = 0; kt < NT; kt++) {
        const int b = kt & 1;
        __syncthreads();                       // B1: buf ready (loads + convert)
        const uint32_t stb = sb + b * BUF;
#pragma unroll
        for (int k16 = 0; k16 < 2; k16++) {
            const int kk = k16 * 32;
            uint32_t afr[4][4], bfr[NF][2];
#pragma unroll
            for (int pa = 0; pa < 3; pa++) {
                const uint32_t abase = stb + pa * TILE_A_B + kk + a_kc;
#pragma unroll
                for (int mf = 0; mf < 4; mf++)
                    ldsm_x4(afr[mf][0], afr[mf][1], afr[mf][2], afr[mf][3],
                            abase + (mbase + mf * 16 + a_r) * TROW);
                const int npb = (pa == 0) ? 3 : (pa == 1) ? 2 : 1;
#pragma unroll
                for (int pb = 0; pb < 3; pb++) {
                    if (pb >= npb) break;
                    const uint32_t bbase = stb + APL_B + pb * TILE_BB + kk + b_kc;
#pragma unroll
                    for (int nf2 = 0; nf2 < NF / 2; nf2++) {
                        uint32_t r0, r1, r2, r3;
                        ldsm_x4(r0, r1, r2, r3,
                                bbase + (nbase + nf2 * 16 + b_n) * TROW);
                        bfr[nf2 * 2 + 0][0] = r0; bfr[nf2 * 2 + 0][1] = r1;
                        bfr[nf2 * 2 + 1][0] = r2; bfr[nf2 * 2 + 1][1] = r3;
                    }
#pragma unroll
                    for (int mf = 0; mf < 4; mf++)
#pragma unroll
                        for (int nf = 0; nf < NF; nf++)
                            hmma16816(acc[mf][nf], afr[mf], bfr[nf]);
                }
            }
        }
        __syncthreads();                       // B2: all warps done with buf
        if (kt + 2 < NT) { load_kt(kt + 2, b); CP_COMMIT(); }
        if (kt + 1 < NT) {
            if (kt + 2 < NT) asm volatile("cp.async.wait_group 1;");
            else             asm volatile("cp.async.wait_group 0;");
            convert_own(b ^ 1);                // overlaps tensor drain of MMA(kt)
        }
    }

    // ---- epilogue: bias + relu -> fp32 ----
    const int qr = lane >> 2, qc = (lane & 3) * 2;
#pragma unroll
    for (int mf = 0; mf < 4; mf++) {
#pragma unroll
        for (int half = 0; half < 2; half++) {
            const int row = brow + mbase + mf * 16 + qr + half * 8;
#pragma unroll
            for (int nf = 0; nf < NF; nf++) {
                const int colL = nbase + nf * 8 + qc;
                float v0 = fmaxf(acc[mf][nf][half * 2 + 0] + sbias[colL],     0.f);
                float v1 = fmaxf(acc[mf][nf][half * 2 + 1] + sbias[colL + 1], 0.f);
                *(float2*)(Cout + (size_t)row * ldN + bcol + colL) = make_float2(v0, v1);
            }
        }
    }
}

#define HS256 (2 * (APL_B + 3 * (256 * TROW) + FST_B))   // 221184
#define HS128 (2 * (APL_B + 3 * (128 * TROW) + FST_B))   // 159744

// ---------------- SIMT FFMA2 GEMM (D-chain) ----------------------------------
__device__ __forceinline__ float act_apply(float v, int ACT) {
    if (ACT == 1) return v > 0.f ? v : 0.f;
    if (ACT == 2) return __fdividef(1.f, 1.f + __expf(-v));
    return v;
}

template<int BM, int BN, int BK, int ACT>
__global__ void __launch_bounds__((BM / 16) * (BN / 4), 2)
gemm2(const float* __restrict__ A, const float* __restrict__ W,
      const float* __restrict__ bias, float* __restrict__ Cmat,
      int K, int N)
{
    constexpr int TN = 4;
    constexpr int RX = BN / TN, RY = BM / 16, THREADS = RX * RY;
    constexpr int GROUPS = THREADS / BM;
    constexpr int KC  = BK / GROUPS;
    constexpr int AF4 = KC / 4;
    constexpr int WC  = (BK * BN) / (4 * THREADS);
    constexpr int BMP = BM + 4;
    constexpr int N4  = BN / 4;

    extern __shared__ float smemf[];
    float (*As)[BK][BMP] = (float (*)[BK][BMP])smemf;
    float (*Ws)[BK][BN]  = (float (*)[BK][BN])(smemf + 2 * BK * BMP);

    const int tid  = threadIdx.x;
    const int tcol = tid % RX;
    const int trow = tid / RX;
    const int brow = blockIdx.y * BM;
    const int bcol = blockIdx.x * BN;

    const int arow = tid % BM;
    const int akb  = (tid / BM) * KC;
    const float* Arow = A + (size_t)(brow + arow) * K + akb;

    ull acc2[8][TN];
#pragma unroll
    for (int i = 0; i < 8; i++)
#pragma unroll
        for (int j = 0; j < TN; j++) acc2[i][j] = 0ull;

    float4 areg[AF4];
    const int nt = K / BK;

#pragma unroll
    for (int q = 0; q < AF4; q++) areg[q] = *(const float4*)(Arow + q * 4);
#pragma unroll
    for (int i = 0; i < WC; i++) {
        int idx = tid + i * THREADS;
        int k = idx / N4, n4 = idx % N4;
        cp_async16(&Ws[0][k][n4 * 4], W + (size_t)k * N + bcol + n4 * 4);
    }
    CP_COMMIT();
#pragma unroll
    for (int q = 0; q < AF4; q++) {
        As[0][akb + q * 4 + 0][arow] = areg[q].x;
        As[0][akb + q * 4 + 1][arow] = areg[q].y;
        As[0][akb + q * 4 + 2][arow] = areg[q].z;
        As[0][akb + q * 4 + 3][arow] = areg[q].w;
    }
    asm volatile("cp.async.wait_group 0;");
    __syncthreads();

    for (int t = 0; t < nt; t++) {
        const int cb = t & 1;
        const bool more = (t + 1 < nt);
        if (more) {
            const float* Ap2 = Arow + (size_t)(t + 1) * BK;
#pragma unroll
            for (int q = 0; q < AF4; q++) areg[q] = *(const float4*)(Ap2 + q * 4);
            const float* Wp = W + (size_t)(t + 1) * BK * N + bcol;
#pragma unroll
            for (int i = 0; i < WC; i++) {
                int idx = tid + i * THREADS;
                int k = idx / N4, n4 = idx % N4;
                cp_async16(&Ws[cb ^ 1][k][n4 * 4], Wp + (size_t)k * N + n4 * 4);
            }
            CP_COMMIT();
        }
#pragma unroll
        for (int k = 0; k < BK; k++) {
            float4 wv = *(const float4*)&Ws[cb][k][tcol * 4];
            ull wb0, wb1, wb2, wb3;
            asm("mov.b64 %0, {%1, %1};" : "=l"(wb0) : "f"(wv.x));
            asm("mov.b64 %0, {%1, %1};" : "=l"(wb1) : "f"(wv.y));
            asm("mov.b64 %0, {%1, %1};" : "=l"(wb2) : "f"(wv.z));
            asm("mov.b64 %0, {%1, %1};" : "=l"(wb3) : "f"(wv.w));
            const float* ab = &As[cb][k][trow * 16];
            ulonglong2 p01 = *(const ulonglong2*)(ab + 0);
            ulonglong2 p23 = *(const ulonglong2*)(ab + 4);
            ulonglong2 p45 = *(const ulonglong2*)(ab + 8);
            ulonglong2 p67 = *(const ulonglong2*)(ab + 12);
            ull ap[8] = {p01.x, p01.y, p23.x, p23.y, p45.x, p45.y, p67.x, p67.y};
#pragma unroll
            for (int i = 0; i < 8; i++) {
                asm("fma.rn.f32x2 %0, %1, %2, %0;" : "+l"(acc2[i][0]) : "l"(ap[i]), "l"(wb0));
                asm("fma.rn.f32x2 %0, %1, %2, %0;" : "+l"(acc2[i][1]) : "l"(ap[i]), "l"(wb1));
                asm("fma.rn.f32x2 %0, %1, %2, %0;" : "+l"(acc2[i][2]) : "l"(ap[i]), "l"(wb2));
                asm("fma.rn.f32x2 %0, %1, %2, %0;" : "+l"(acc2[i][3]) : "l"(ap[i]), "l"(wb3));
            }
        }
        if (more) {
#pragma unroll
            for (int q = 0; q < AF4; q++) {
                As[cb ^ 1][akb + q * 4 + 0][arow] = areg[q].x;
                As[cb ^ 1][akb + q * 4 + 1][arow] = areg[q].y;
                As[cb ^ 1][akb + q * 4 + 2][arow] = areg[q].z;
                As[cb ^ 1][akb + q * 4 + 3][arow] = areg[q].w;
            }
            asm volatile("cp.async.wait_group 0;");
        }
        __syncthreads();
    }

    const int colb = bcol + tcol * 4;
    float4 bv = *(const float4*)(bias + colb);
#pragma unroll
    for (int i2 = 0; i2 < 8; i2++) {
        int row0 = brow + trow * 16 + 2 * i2;
        float e0, o0, e1, o1, e2, o2, e3, o3;
        asm("mov.b64 {%0, %1}, %2;" : "=f"(e0), "=f"(o0) : "l"(acc2[i2][0]));
        asm("mov.b64 {%0, %1}, %2;" : "=f"(e1), "=f"(o1) : "l"(acc2[i2][1]));
        asm("mov.b64 {%0, %1}, %2;" : "=f"(e2), "=f"(o2) : "l"(acc2[i2][2]));
        asm("mov.b64 {%0, %1}, %2;" : "=f"(e3), "=f"(o3) : "l"(acc2[i2][3]));
        float4 re, ro;
        re.x = act_apply(e0 + bv.x, ACT); re.y = act_apply(e1 + bv.y, ACT);
        re.z = act_apply(e2 + bv.z, ACT); re.w = act_apply(e3 + bv.w, ACT);
        ro.x = act_apply(o0 + bv.x, ACT); ro.y = act_apply(o1 + bv.y, ACT);
        ro.z = act_apply(o2 + bv.z, ACT); ro.w = act_apply(o3 + bv.w, ACT);
        *(float4*)(Cmat + (size_t)row0 * N + colb)       = re;
        *(float4*)(Cmat + (size_t)(row0 + 1) * N + colb) = ro;
    }
}

// d[r] = d2[r,:] . D3 + db3   (K = 64)
__global__ void dot_kernel(const float* __restrict__ d2, const float* __restrict__ D3,
                           const float* __restrict__ db3, float* __restrict__ dd)
{
    int gw   = (blockIdx.x * blockDim.x + threadIdx.x) >> 5;
    int lane = threadIdx.x & 31;
    if (gw >= MR) return;
    const float* row = d2 + (size_t)gw * 64;
    float s = row[lane] * D3[lane] + row[lane + 32] * D3[lane + 32];
#pragma unroll
    for (int o = 16; o > 0; o >>= 1) s += __shfl_down_sync(0xffffffffu, s, o);
    if (lane == 0) dd[gw] = s + db3[0];
}

// Per-bag: gumbel softmax, top-20 keep (stable), re-softmax, aggregate, project.
__global__ void __launch_bounds__(128)
final_kernel(const float* __restrict__ dd, const float* __restrict__ m,
             const float* __restrict__ u, const float* __restrict__ h3,
             const float* __restrict__ E, const float* __restrict__ eb,
             float* __restrict__ out_w, float* __restrict__ out_s)
{
    const int bag = blockIdx.x;
    const int t   = threadIdx.x;

    __shared__ float sm[64];
    __shared__ float wf[64];
    __shared__ float red[128];

    float z = 0.f;
    if (t < 64) {
        float logit = m[bag * 64 + t] * dd[bag * 64 + t];
        float uu = u[bag * 64 + t];
        float g = -logf(-logf(uu));
        z = (logit + g) / TAU_F;
    }

    red[t] = (t < 64) ? z : -INFINITY;
    __syncthreads();
#pragma unroll
    for (int s = 64; s >= 1; s >>= 1) {
        if (t < s) red[t] = fmaxf(red[t], red[t + s]);
        __syncthreads();
    }
    float zmax = red[0];
    __syncthreads();

    float e = (t < 64) ? expf(z - zmax) : 0.f;
    red[t] = e;
    __syncthreads();
#pragma unroll
    for (int s = 64; s >= 1; s >>= 1) {
        if (t < s) red[t] += red[t + s];
        __syncthreads();
    }
    float psum = red[0];
    __syncthreads();

    float p = e / psum;
    if (t < 64) sm[t] = p;
    __syncthreads();

    int keep = 0;
    if (t < 64) {
        int pos = 0;
#pragma unroll 8
        for (int j = 0; j < 64; j++) {
            float o = sm[j];
            pos += (o < p) || (o == p && j < t);
        }
        keep = (pos >= 44);
    }

    red[t] = (t < 64 && keep) ? p : -INFINITY;
    __syncthreads();
#pragma unroll
    for (int s = 64; s >= 1; s >>= 1) {
        if (t < s) red[t] = fmaxf(red[t], red[t + s]);
        __syncthreads();
    }
    float m2 = red[0];
    __syncthreads();

    float e2 = (t < 64 && keep) ? expf(p - m2) : 0.f;
    red[t] = e2;
    __syncthreads();
#pragma unroll
    for (int s = 64; s >= 1; s >>= 1) {
        if (t < s) red[t] += red[t + s];
        __syncthreads();
    }
    float s2 = red[0];
    __syncthreads();

    float wfin = (t < 64 && keep) ? (e2 / s2) : 0.f;
    if (t < 64) {
        wf[t] = wfin;
        out_w[bag * 64 + t] = wfin;
    }
    __syncthreads();

    const float* hb = h3 + (size_t)bag * 64 * 128;
    float agg = 0.f;
#pragma unroll 8
    for (int c = 0; c < 64; c++) agg += wf[c] * hb[c * 128 + t];
    red[t] = agg * E[t];
    __syncthreads();
#pragma unroll
    for (int s = 64; s >= 1; s >>= 1) {
        if (t < s) red[t] += red[t + s];
        __syncthreads();
    }
    if (t == 0) out_s[bag] = red[0] + eb[0];
}

// ---------------- launch ------------------------------------------------------
extern "C" void kernel_launch(void* const* d_in, const int* in_sizes, int n_in,
                              void* d_out, int out_size)
{
    const float* x   = (const float*)d_in[0];
    const float* m   = (const float*)d_in[1];
    const float* u   = (const float*)d_in[2];
    const float* W1  = (const float*)d_in[3];
    const float* b1  = (const float*)d_in[4];
    const float* W2  = (const float*)d_in[5];
    const float* b2  = (const float*)d_in[6];
    const float* W3  = (const float*)d_in[7];
    const float* b3  = (const float*)d_in[8];
    const float* D1  = (const float*)d_in[9];
    const float* db1 = (const float*)d_in[10];
    const float* D2  = (const float*)d_in[11];
    const float* db2 = (const float*)d_in[12];
    const float* D3  = (const float*)d_in[13];
    const float* db3 = (const float*)d_in[14];
    const float* E   = (const float*)d_in[15];
    const float* eb  = (const float*)d_in[16];
    float* out = (float*)d_out;

    __nv_bfloat16 *w1t, *w2t, *w3t;
    float *h1f, *h2f, *h3, *d1, *d2, *dd;
    cudaGetSymbolAddress((void**)&w1t, g_w1t);
    cudaGetSymbolAddress((void**)&w2t, g_w2t);
    cudaGetSymbolAddress((void**)&w3t, g_w3t);
    cudaGetSymbolAddress((void**)&h1f, g_h1f);
    cudaGetSymbolAddress((void**)&h2f, g_h2f);
    cudaGetSymbolAddress((void**)&h3,  g_h3);
    cudaGetSymbolAddress((void**)&d1,  g_d1);
    cudaGetSymbolAddress((void**)&d2,  g_d2);
    cudaGetSymbolAddress((void**)&dd,  g_dd);

    constexpr int S128 = (2 * 32 * 132 + 2 * 32 * 128) * 4;
    constexpr int S64  = (2 * 16 * 132 + 2 * 16 * 64) * 4;

    static int attr_done = 0;
    if (!attr_done) {
        cudaFuncSetAttribute(hmma_gemm<256>, cudaFuncAttributeMaxDynamicSharedMemorySize, HS256);
        cudaFuncSetAttribute(hmma_gemm<128>, cudaFuncAttributeMaxDynamicSharedMemorySize, HS128);
        cudaFuncSetAttribute(gemm2<128,128,32,2>, cudaFuncAttributeMaxDynamicSharedMemorySize, S128);
        cudaFuncSetAttribute(gemm2<128, 64,16,2>, cudaFuncAttributeMaxDynamicSharedMemorySize, S64);
        attr_done = 1;
    }

    // weight splits (tiny)
    split_wt_kernel<<<(512 * 256 + 255) / 256, 256>>>(W1, w1t, 512, 256);
    split_wt_kernel<<<(256 * 256 + 255) / 256, 256>>>(W2, w2t, 256, 256);
    split_wt_kernel<<<(256 * 128 + 255) / 256, 256>>>(W3, w3t, 256, 128);

    // h-chain on HMMA (exact-fp32 via 3-split/6-product), BN=256 tiles
    hmma_gemm<256><<<dim3(1, MR / 128), 256, HS256>>>(x,   w1t, b1, h1f, 512, 256);
    hmma_gemm<256><<<dim3(1, MR / 128), 256, HS256>>>(h1f, w2t, b2, h2f, 256, 256);
    hmma_gemm<128><<<dim3(1, MR / 128), 256, HS128>>>(h2f, w3t, b3, h3,  256, 128);

    // D-chain (SIMT FFMA2)
    gemm2<128,128,32,2><<<dim3(1, MR / 128), 256, S128>>>(h3, D1, db1, d1, 128, 128);
    gemm2<128, 64,16,2><<<dim3(1, MR / 128), 128, S64>>>(d1, D2, db2, d2, 128, 64);
    dot_kernel<<<MR / 8, 256>>>(d2, D3, db3, dd);
    final_kernel<<<NB, 128>>>(dd, m, u, h3, E, eb, out, out + MR);
}

// round 13
// speedup vs baseline: 1.8287x; 1.5481x over previous
#include <cuda_runtime.h>
#include <cuda_fp16.h>
#include <math.h>
#include <stdint.h>

// ---------------------------------------------------------------------------
// BagAttentionNet forward.
//   h-chain (512->256->256->128, relu) on mma.sync fp16 (HMMA) with
//   2-split/3-product near-fp32 emulation (~2^-23). BN=256 CTA tiles.
//   fp32 in / in-kernel split / fp32 out. D-chain + tail: SIMT fp32 (FFMA2).
// ---------------------------------------------------------------------------

#define NB 2048
#define CI 64
#define MR (NB * CI)          // 131072
#define TAU_F 0.95f

typedef unsigned long long ull;

// ---------------- scratch (__device__ globals; no allocs allowed) ----------
__device__ float g_h1f[(size_t)MR * 256];
__device__ float g_h2f[(size_t)MR * 256];
__device__ float g_h3 [(size_t)MR * 128];
__device__ float g_d1 [(size_t)MR * 128];
__device__ float g_d2 [(size_t)MR * 64];
__device__ float g_dd [MR];
__device__ __half g_w1t[2 * 512 * 256];     // W1^T planes [2][256][512]
__device__ __half g_w2t[2 * 256 * 256];     // W2^T planes [2][256][256]
__device__ __half g_w3t[2 * 256 * 128];     // W3^T planes [2][128][256]

// ---------------- helpers ----------------------------------------------------
__device__ __forceinline__ void cp_async16(void* s, const void* g) {
    unsigned sa = (unsigned)__cvta_generic_to_shared(s);
    asm volatile("cp.async.cg.shared.global [%0], [%1], 16;" :: "r"(sa), "l"(g));
}
#define CP_COMMIT() asm volatile("cp.async.commit_group;")

__device__ __forceinline__ void split2(float v, __half& h, __half& m) {
    h = __float2half(v);
    m = __float2half(v - __half2float(h));
}

__device__ __forceinline__ void ldsm_x4(uint32_t& r0, uint32_t& r1,
                                        uint32_t& r2, uint32_t& r3, uint32_t addr) {
    asm volatile("ldmatrix.sync.aligned.m8n8.x4.shared.b16 {%0,%1,%2,%3},[%4];"
        : "=r"(r0), "=r"(r1), "=r"(r2), "=r"(r3) : "r"(addr));
}

__device__ __forceinline__ void hmma16816(float* c, const uint32_t* a, const uint32_t* b) {
    asm volatile("mma.sync.aligned.m16n8k16.row.col.f32.f16.f16.f32 "
        "{%0,%1,%2,%3},{%4,%5,%6,%7},{%8,%9},{%0,%1,%2,%3};"
        : "+f"(c[0]), "+f"(c[1]), "+f"(c[2]), "+f"(c[3])
        : "r"(a[0]), "r"(a[1]), "r"(a[2]), "r"(a[3]), "r"(b[0]), "r"(b[1]));
}

// W[K][N] -> planes [2][N][K] (transpose + 2-split fp16)
__global__ void split_wt_kernel(const float* __restrict__ W,
                                __half* __restrict__ o, int K, int N) {
    int idx = blockIdx.x * blockDim.x + threadIdx.x;
    if (idx >= K * N) return;
    int k = idx / N, n = idx % N;
    __half h, m;
    split2(W[idx], h, m);
    size_t pl = (size_t)K * N;
    size_t off = (size_t)n * K + k;
    o[off] = h; o[pl + off] = m;
}

// ---------------- HMMA 2-split GEMM (BN-wide CTA tile) -----------------------
// A: fp32 [M][K]. B: 2 fp16 planes [2][ldN][K] (=W^T). Out: fp32 relu [M][ldN].
// Products: hh, hm, mh (mm dropped, ~2^-24). CTA tile 128 x BN.
#define TROW 80                            // 64B data + 16B pad
#define TILE_A_B (128 * TROW)              // 10240 (one A plane tile)
#define APL_B (2 * TILE_A_B)               // 20480
#define FST_B (128 * 144)                  // 18432 (fp32 stage, 36-float stride)

template<int BN>
__global__ void __launch_bounds__(256, 1)
hmma_gemm(const float* __restrict__ Af, const __half* __restrict__ Bp,
          const float* __restrict__ bias, float* __restrict__ Cout,
          int K, int ldN)
{
    constexpr int TILE_BB = BN * TROW;         // one B plane tile bytes
    constexpr int BPL = 2 * TILE_BB;
    constexpr int BUF = APL_B + BPL + FST_B;
    constexpr int NF = BN / 32;                // n-fragments per warp (8 or 4)
    constexpr int NB_IT = BN / 32;             // B chunks per thread (8*BN/256)

    extern __shared__ char smem[];
    __shared__ float sbias[BN];
    const uint32_t sb = (uint32_t)__cvta_generic_to_shared(smem);
    const int tid = threadIdx.x, wid = tid >> 5, lane = tid & 31;
    const int brow = blockIdx.y * 128, bcol = blockIdx.x * BN;
    const int mbase = (wid >> 2) * 64;
    const int nbase = (wid & 3) * (BN / 4);
    const size_t bplane = (size_t)ldN * K;
    const int NT = K / 32;

    if (tid < BN) sbias[tid] = bias[bcol + tid];

    const char* Bg = (const char*)Bp;

    auto load_kt = [&](int kt, int b) {
        char* st = smem + b * BUF;
        // B planes: 8*BN chunks total
#pragma unroll
        for (int i = 0; i < NB_IT; i++) {
            int c = tid + i * 256;
            int p = c / (BN * 4), rem = c % (BN * 4);
            int row = rem >> 2, col4 = rem & 3;
            cp_async16(st + APL_B + p * TILE_BB + row * TROW + col4 * 16,
                Bg + ((size_t)p * bplane + (size_t)(bcol + row) * K) * 2
                   + (size_t)kt * 64 + col4 * 16);
        }
        // fp32 A tile: 1024 chunks, 4 per thread
        char* fs = st + APL_B + BPL;
#pragma unroll
        for (int i = 0; i < 4; i++) {
            int c = tid + i * 256;
            int row = c >> 3, col = c & 7;
            cp_async16(fs + row * 144 + col * 16,
                (const char*)(Af + (size_t)(brow + row) * K + kt * 32 + col * 4));
        }
    };

    auto convert_own = [&](int b) {
        const float* fs = (const float*)(smem + b * BUF + APL_B + BPL);
        char* ap = smem + b * BUF;
#pragma unroll
        for (int i = 0; i < 4; i++) {
            int c = tid + i * 256;
            int row = c >> 3, col = c & 7;
            float4 v = *(const float4*)(fs + row * 36 + col * 4);
            float vv[4] = {v.x, v.y, v.z, v.w};
            __half h[4], mm[4];
#pragma unroll
            for (int e = 0; e < 4; e++) split2(vv[e], h[e], mm[e]);
            const uint32_t off = row * TROW + col * 8;
            *(__half2*)(ap + off)                = __halves2half2(h[0], h[1]);
            *(__half2*)(ap + off + 4)            = __halves2half2(h[2], h[3]);
            *(__half2*)(ap + TILE_A_B + off)     = __halves2half2(mm[0], mm[1]);
            *(__half2*)(ap + TILE_A_B + off + 4) = __halves2half2(mm[2], mm[3]);
        }
    };

    float acc[4][NF][4];
#pragma unroll
    for (int i = 0; i < 4; i++)
#pragma unroll
        for (int j = 0; j < NF; j++)
#pragma unroll
            for (int q = 0; q < 4; q++) acc[i][j][q] = 0.f;

    load_kt(0, 0); CP_COMMIT();
    load_kt(1, 1); CP_COMMIT();
    asm volatile("cp.async.wait_group 1;");
    convert_own(0);

    const int a_r  = (lane & 15);
    const int a_kc = (lane & 16) ? 16 : 0;
    const int b_n  = (lane & 7) + ((lane & 16) ? 8 : 0);
    const int b_kc = (lane & 8) ? 16 : 0;

    for (int kt = 0; kt < NT; kt++) {
        const int b = kt & 1;
        __syncthreads();                       // B1: buf ready (loads + convert)
        const uint32_t stb = sb + b * BUF;
#pragma unroll
        for (int k16 = 0; k16 < 2; k16++) {
            const int kk = k16 * 32;
            uint32_t afr[4][4], bfr[NF][2];
#pragma unroll
            for (int pa = 0; pa < 2; pa++) {
                const uint32_t abase = stb + pa * TILE_A_B + kk + a_kc;
#pragma unroll
                for (int mf = 0; mf < 4; mf++)
                    ldsm_x4(afr[mf][0], afr[mf][1], afr[mf][2], afr[mf][3],
                            abase + (mbase + mf * 16 + a_r) * TROW);
                const int npb = 2 - pa;        // hh,hm then mh
#pragma unroll
                for (int pb = 0; pb < 2; pb++) {
                    if (pb >= npb) break;
                    const uint32_t bbase = stb + APL_B + pb * TILE_BB + kk + b_kc;
#pragma unroll
                    for (int nf2 = 0; nf2 < NF / 2; nf2++) {
                        uint32_t r0, r1, r2, r3;
                        ldsm_x4(r0, r1, r2, r3,
                                bbase + (nbase + nf2 * 16 + b_n) * TROW);
                        bfr[nf2 * 2 + 0][0] = r0; bfr[nf2 * 2 + 0][1] = r1;
                        bfr[nf2 * 2 + 1][0] = r2; bfr[nf2 * 2 + 1][1] = r3;
                    }
#pragma unroll
                    for (int mf = 0; mf < 4; mf++)
#pragma unroll
                        for (int nf = 0; nf < NF; nf++)
                            hmma16816(acc[mf][nf], afr[mf], bfr[nf]);
                }
            }
        }
        __syncthreads();                       // B2: all warps done with buf
        if (kt + 2 < NT) { load_kt(kt + 2, b); CP_COMMIT(); }
        if (kt + 1 < NT) {
            if (kt + 2 < NT) asm volatile("cp.async.wait_group 1;");
            else             asm volatile("cp.async.wait_group 0;");
            convert_own(b ^ 1);                // overlaps tensor drain of MMA(kt)
        }
    }

    // ---- epilogue: bias + relu -> fp32 ----
    const int qr = lane >> 2, qc = (lane & 3) * 2;
#pragma unroll
    for (int mf = 0; mf < 4; mf++) {
#pragma unroll
        for (int half = 0; half < 2; half++) {
            const int row = brow + mbase + mf * 16 + qr + half * 8;
#pragma unroll
            for (int nf = 0; nf < NF; nf++) {
                const int colL = nbase + nf * 8 + qc;
                float v0 = fmaxf(acc[mf][nf][half * 2 + 0] + sbias[colL],     0.f);
                float v1 = fmaxf(acc[mf][nf][half * 2 + 1] + sbias[colL + 1], 0.f);
                *(float2*)(Cout + (size_t)row * ldN + bcol + colL) = make_float2(v0, v1);
            }
        }
    }
}

#define HS256 (2 * (APL_B + 2 * (256 * TROW) + FST_B))   // 159744
#define HS128 (2 * (APL_B + 2 * (128 * TROW) + FST_B))   // 118784

// ---------------- SIMT FFMA2 GEMM (D-chain) ----------------------------------
__device__ __forceinline__ float act_apply(float v, int ACT) {
    if (ACT == 1) return v > 0.f ? v : 0.f;
    if (ACT == 2) return __fdividef(1.f, 1.f + __expf(-v));
    return v;
}

template<int BM, int BN, int BK, int ACT>
__global__ void __launch_bounds__((BM / 16) * (BN / 4), 2)
gemm2(const float* __restrict__ A, const float* __restrict__ W,
      const float* __restrict__ bias, float* __restrict__ Cmat,
      int K, int N)
{
    constexpr int TN = 4;
    constexpr int RX = BN / TN, RY = BM / 16, THREADS = RX * RY;
    constexpr int GROUPS = THREADS / BM;
    constexpr int KC  = BK / GROUPS;
    constexpr int AF4 = KC / 4;
    constexpr int WC  = (BK * BN) / (4 * THREADS);
    constexpr int BMP = BM + 4;
    constexpr int N4  = BN / 4;

    extern __shared__ float smemf[];
    float (*As)[BK][BMP] = (float (*)[BK][BMP])smemf;
    float (*Ws)[BK][BN]  = (float (*)[BK][BN])(smemf + 2 * BK * BMP);

    const int tid  = threadIdx.x;
    const int tcol = tid % RX;
    const int trow = tid / RX;
    const int brow = blockIdx.y * BM;
    const int bcol = blockIdx.x * BN;

    const int arow = tid % BM;
    const int akb  = (tid / BM) * KC;
    const float* Arow = A + (size_t)(brow + arow) * K + akb;

    ull acc2[8][TN];
#pragma unroll
    for (int i = 0; i < 8; i++)
#pragma unroll
        for (int j = 0; j < TN; j++) acc2[i][j] = 0ull;

    float4 areg[AF4];
    const int nt = K / BK;

#pragma unroll
    for (int q = 0; q < AF4; q++) areg[q] = *(const float4*)(Arow + q * 4);
#pragma unroll
    for (int i = 0; i < WC; i++) {
        int idx = tid + i * THREADS;
        int k = idx / N4, n4 = idx % N4;
        cp_async16(&Ws[0][k][n4 * 4], W + (size_t)k * N + bcol + n4 * 4);
    }
    CP_COMMIT();
#pragma unroll
    for (int q = 0; q < AF4; q++) {
        As[0][akb + q * 4 + 0][arow] = areg[q].x;
        As[0][akb + q * 4 + 1][arow] = areg[q].y;
        As[0][akb + q * 4 + 2][arow] = areg[q].z;
        As[0][akb + q * 4 + 3][arow] = areg[q].w;
    }
    asm volatile("cp.async.wait_group 0;");
    __syncthreads();

    for (int t = 0; t < nt; t++) {
        const int cb = t & 1;
        const bool more = (t + 1 < nt);
        if (more) {
            const float* Ap2 = Arow + (size_t)(t + 1) * BK;
#pragma unroll
            for (int q = 0; q < AF4; q++) areg[q] = *(const float4*)(Ap2 + q * 4);
            const float* Wp = W + (size_t)(t + 1) * BK * N + bcol;
#pragma unroll
            for (int i = 0; i < WC; i++) {
                int idx = tid + i * THREADS;
                int k = idx / N4, n4 = idx % N4;
                cp_async16(&Ws[cb ^ 1][k][n4 * 4], Wp + (size_t)k * N + n4 * 4);
            }
            CP_COMMIT();
        }
#pragma unroll
        for (int k = 0; k < BK; k++) {
            float4 wv = *(const float4*)&Ws[cb][k][tcol * 4];
            ull wb0, wb1, wb2, wb3;
            asm("mov.b64 %0, {%1, %1};" : "=l"(wb0) : "f"(wv.x));
            asm("mov.b64 %0, {%1, %1};" : "=l"(wb1) : "f"(wv.y));
            asm("mov.b64 %0, {%1, %1};" : "=l"(wb2) : "f"(wv.z));
            asm("mov.b64 %0, {%1, %1};" : "=l"(wb3) : "f"(wv.w));
            const float* ab = &As[cb][k][trow * 16];
            ulonglong2 p01 = *(const ulonglong2*)(ab + 0);
            ulonglong2 p23 = *(const ulonglong2*)(ab + 4);
            ulonglong2 p45 = *(const ulonglong2*)(ab + 8);
            ulonglong2 p67 = *(const ulonglong2*)(ab + 12);
            ull ap[8] = {p01.x, p01.y, p23.x, p23.y, p45.x, p45.y, p67.x, p67.y};
#pragma unroll
            for (int i = 0; i < 8; i++) {
                asm("fma.rn.f32x2 %0, %1, %2, %0;" : "+l"(acc2[i][0]) : "l"(ap[i]), "l"(wb0));
                asm("fma.rn.f32x2 %0, %1, %2, %0;" : "+l"(acc2[i][1]) : "l"(ap[i]), "l"(wb1));
                asm("fma.rn.f32x2 %0, %1, %2, %0;" : "+l"(acc2[i][2]) : "l"(ap[i]), "l"(wb2));
                asm("fma.rn.f32x2 %0, %1, %2, %0;" : "+l"(acc2[i][3]) : "l"(ap[i]), "l"(wb3));
            }
        }
        if (more) {
#pragma unroll
            for (int q = 0; q < AF4; q++) {
                As[cb ^ 1][akb + q * 4 + 0][arow] = areg[q].x;
                As[cb ^ 1][akb + q * 4 + 1][arow] = areg[q].y;
                As[cb ^ 1][akb + q * 4 + 2][arow] = areg[q].z;
                As[cb ^ 1][akb + q * 4 + 3][arow] = areg[q].w;
            }
            asm volatile("cp.async.wait_group 0;");
        }
        __syncthreads();
    }

    const int colb = bcol + tcol * 4;
    float4 bv = *(const float4*)(bias + colb);
#pragma unroll
    for (int i2 = 0; i2 < 8; i2++) {
        int row0 = brow + trow * 16 + 2 * i2;
        float e0, o0, e1, o1, e2, o2, e3, o3;
        asm("mov.b64 {%0, %1}, %2;" : "=f"(e0), "=f"(o0) : "l"(acc2[i2][0]));
        asm("mov.b64 {%0, %1}, %2;" : "=f"(e1), "=f"(o1) : "l"(acc2[i2][1]));
        asm("mov.b64 {%0, %1}, %2;" : "=f"(e2), "=f"(o2) : "l"(acc2[i2][2]));
        asm("mov.b64 {%0, %1}, %2;" : "=f"(e3), "=f"(o3) : "l"(acc2[i2][3]));
        float4 re, ro;
        re.x = act_apply(e0 + bv.x, ACT); re.y = act_apply(e1 + bv.y, ACT);
        re.z = act_apply(e2 + bv.z, ACT); re.w = act_apply(e3 + bv.w, ACT);
        ro.x = act_apply(o0 + bv.x, ACT); ro.y = act_apply(o1 + bv.y, ACT);
        ro.z = act_apply(o2 + bv.z, ACT); ro.w = act_apply(o3 + bv.w, ACT);
        *(float4*)(Cmat + (size_t)row0 * N + colb)       = re;
        *(float4*)(Cmat + (size_t)(row0 + 1) * N + colb) = ro;
    }
}

// d[r] = d2[r,:] . D3 + db3   (K = 64)
__global__ void dot_kernel(const float* __restrict__ d2, const float* __restrict__ D3,
                           const float* __restrict__ db3, float* __restrict__ dd)
{
    int gw   = (blockIdx.x * blockDim.x + threadIdx.x) >> 5;
    int lane = threadIdx.x & 31;
    if (gw >= MR) return;
    const float* row = d2 + (size_t)gw * 64;
    float s = row[lane] * D3[lane] + row[lane + 32] * D3[lane + 32];
#pragma unroll
    for (int o = 16; o > 0; o >>= 1) s += __shfl_down_sync(0xffffffffu, s, o);
    if (lane == 0) dd[gw] = s + db3[0];
}

// Per-bag: gumbel softmax, top-20 keep (stable), re-softmax, aggregate, project.
__global__ void __launch_bounds__(128)
final_kernel(const float* __restrict__ dd, const float* __restrict__ m,
             const float* __restrict__ u, const float* __restrict__ h3,
             const float* __restrict__ E, const float* __restrict__ eb,
             float* __restrict__ out_w, float* __restrict__ out_s)
{
    const int bag = blockIdx.x;
    const int t   = threadIdx.x;

    __shared__ float sm[64];
    __shared__ float wf[64];
    __shared__ float red[128];

    float z = 0.f;
    if (t < 64) {
        float logit = m[bag * 64 + t] * dd[bag * 64 + t];
        float uu = u[bag * 64 + t];
        float g = -logf(-logf(uu));
        z = (logit + g) / TAU_F;
    }

    red[t] = (t < 64) ? z : -INFINITY;
    __syncthreads();
#pragma unroll
    for (int s = 64; s >= 1; s >>= 1) {
        if (t < s) red[t] = fmaxf(red[t], red[t + s]);
        __syncthreads();
    }
    float zmax = red[0];
    __syncthreads();

    float e = (t < 64) ? expf(z - zmax) : 0.f;
    red[t] = e;
    __syncthreads();
#pragma unroll
    for (int s = 64; s >= 1; s >>= 1) {
        if (t < s) red[t] += red[t + s];
        __syncthreads();
    }
    float psum = red[0];
    __syncthreads();

    float p = e / psum;
    if (t < 64) sm[t] = p;
    __syncthreads();

    int keep = 0;
    if (t < 64) {
        int pos = 0;
#pragma unroll 8
        for (int j = 0; j < 64; j++) {
            float o = sm[j];
            pos += (o < p) || (o == p && j < t);
        }
        keep = (pos >= 44);
    }

    red[t] = (t < 64 && keep) ? p : -INFINITY;
    __syncthreads();
#pragma unroll
    for (int s = 64; s >= 1; s >>= 1) {
        if (t < s) red[t] = fmaxf(red[t], red[t + s]);
        __syncthreads();
    }
    float m2 = red[0];
    __syncthreads();

    float e2 = (t < 64 && keep) ? expf(p - m2) : 0.f;
    red[t] = e2;
    __syncthreads();
#pragma unroll
    for (int s = 64; s >= 1; s >>= 1) {
        if (t < s) red[t] += red[t + s];
        __syncthreads();
    }
    float s2 = red[0];
    __syncthreads();

    float wfin = (t < 64 && keep) ? (e2 / s2) : 0.f;
    if (t < 64) {
        wf[t] = wfin;
        out_w[bag * 64 + t] = wfin;
    }
    __syncthreads();

    const float* hb = h3 + (size_t)bag * 64 * 128;
    float agg = 0.f;
#pragma unroll 8
    for (int c = 0; c < 64; c++) agg += wf[c] * hb[c * 128 + t];
    red[t] = agg * E[t];
    __syncthreads();
#pragma unroll
    for (int s = 64; s >= 1; s >>= 1) {
        if (t < s) red[t] += red[t + s];
        __syncthreads();
    }
    if (t == 0) out_s[bag] = red[0] + eb[0];
}

// ---------------- launch ------------------------------------------------------
extern "C" void kernel_launch(void* const* d_in, const int* in_sizes, int n_in,
                              void* d_out, int out_size)
{
    const float* x   = (const float*)d_in[0];
    const float* m   = (const float*)d_in[1];
    const float* u   = (const float*)d_in[2];
    const float* W1  = (const float*)d_in[3];
    const float* b1  = (const float*)d_in[4];
    const float* W2  = (const float*)d_in[5];
    const float* b2  = (const float*)d_in[6];
    const float* W3  = (const float*)d_in[7];
    const float* b3  = (const float*)d_in[8];
    const float* D1  = (const float*)d_in[9];
    const float* db1 = (const float*)d_in[10];
    const float* D2  = (const float*)d_in[11];
    const float* db2 = (const float*)d_in[12];
    const float* D3  = (const float*)d_in[13];
    const float* db3 = (const float*)d_in[14];
    const float* E   = (const float*)d_in[15];
    const float* eb  = (const float*)d_in[16];
    float* out = (float*)d_out;

    __half *w1t, *w2t, *w3t;
    float *h1f, *h2f, *h3, *d1, *d2, *dd;
    cudaGetSymbolAddress((void**)&w1t, g_w1t);
    cudaGetSymbolAddress((void**)&w2t, g_w2t);
    cudaGetSymbolAddress((void**)&w3t, g_w3t);
    cudaGetSymbolAddress((void**)&h1f, g_h1f);
    cudaGetSymbolAddress((void**)&h2f, g_h2f);
    cudaGetSymbolAddress((void**)&h3,  g_h3);
    cudaGetSymbolAddress((void**)&d1,  g_d1);
    cudaGetSymbolAddress((void**)&d2,  g_d2);
    cudaGetSymbolAddress((void**)&dd,  g_dd);

    constexpr int S128 = (2 * 32 * 132 + 2 * 32 * 128) * 4;
    constexpr int S64  = (2 * 16 * 132 + 2 * 16 * 64) * 4;

    static int attr_done = 0;
    if (!attr_done) {
        cudaFuncSetAttribute(hmma_gemm<256>, cudaFuncAttributeMaxDynamicSharedMemorySize, HS256);
        cudaFuncSetAttribute(hmma_gemm<128>, cudaFuncAttributeMaxDynamicSharedMemorySize, HS128);
        cudaFuncSetAttribute(gemm2<128,128,32,2>, cudaFuncAttributeMaxDynamicSharedMemorySize, S128);
        cudaFuncSetAttribute(gemm2<128, 64,16,2>, cudaFuncAttributeMaxDynamicSharedMemorySize, S64);
        attr_done = 1;
    }

    // weight splits (tiny)
    split_wt_kernel<<<(512 * 256 + 255) / 256, 256>>>(W1, w1t, 512, 256);
    split_wt_kernel<<<(256 * 256 + 255) / 256, 256>>>(W2, w2t, 256, 256);
    split_wt_kernel<<<(256 * 128 + 255) / 256, 256>>>(W3, w3t, 256, 128);

    // h-chain on HMMA (near-fp32 via fp16 2-split/3-product), BN=256 tiles
    hmma_gemm<256><<<dim3(1, MR / 128), 256, HS256>>>(x,   w1t, b1, h1f, 512, 256);
    hmma_gemm<256><<<dim3(1, MR / 128), 256, HS256>>>(h1f, w2t, b2, h2f, 256, 256);
    hmma_gemm<128><<<dim3(1, MR / 128), 256, HS128>>>(h2f, w3t, b3, h3,  256, 128);

    // D-chain (SIMT FFMA2)
    gemm2<128,128,32,2><<<dim3(1, MR / 128), 256, S128>>>(h3, D1, db1, d1, 128, 128);
    gemm2<128, 64,16,2><<<dim3(1, MR / 128), 128, S64>>>(d1, D2, db2, d2, 128, 64);
    dot_kernel<<<MR / 8, 256>>>(d2, D3, db3, dd);
    final_kernel<<<NB, 128>>>(dd, m, u, h3, E, eb, out, out + MR);
}

// round 14
// speedup vs baseline: 2.1575x; 1.1798x over previous
#include <cuda_runtime.h>
#include <cuda_fp16.h>
#include <math.h>
#include <stdint.h>

// ---------------------------------------------------------------------------
// BagAttentionNet forward.
//   All five dense layers on mma.sync fp16 (HMMA) 2-split/3-product
//   near-fp32 emulation. BN=128 tiles, 2 CTAs/SM, A staged via LDG->regs->
//   split2->STS (no fp32 smem stage). dot + softmax/top-k tail: SIMT fp32.
// ---------------------------------------------------------------------------

#define NB 2048
#define CI 64
#define MR (NB * CI)          // 131072
#define TAU_F 0.95f

// ---------------- scratch (__device__ globals; no allocs allowed) ----------
__device__ float g_h1f[(size_t)MR * 256];
__device__ float g_h2f[(size_t)MR * 256];
__device__ float g_h3 [(size_t)MR * 128];
__device__ float g_d1 [(size_t)MR * 128];
__device__ float g_d2 [(size_t)MR * 64];
__device__ float g_dd [MR];
__device__ __half g_w1t [2 * 512 * 256];    // W1^T planes [2][256][512]
__device__ __half g_w2t [2 * 256 * 256];    // W2^T planes [2][256][256]
__device__ __half g_w3t [2 * 256 * 128];    // W3^T planes [2][128][256]
__device__ __half g_dw1t[2 * 128 * 128];    // D1^T planes [2][128][128]
__device__ __half g_dw2t[2 * 128 * 64];     // D2^T planes [2][64][128]

// ---------------- helpers ----------------------------------------------------
__device__ __forceinline__ void cp_async16(void* s, const void* g) {
    unsigned sa = (unsigned)__cvta_generic_to_shared(s);
    asm volatile("cp.async.cg.shared.global [%0], [%1], 16;" :: "r"(sa), "l"(g));
}
#define CP_COMMIT() asm volatile("cp.async.commit_group;")

__device__ __forceinline__ void split2(float v, __half& h, __half& m) {
    h = __float2half(v);
    m = __float2half(v - __half2float(h));
}

__device__ __forceinline__ void ldsm_x4(uint32_t& r0, uint32_t& r1,
                                        uint32_t& r2, uint32_t& r3, uint32_t addr) {
    asm volatile("ldmatrix.sync.aligned.m8n8.x4.shared.b16 {%0,%1,%2,%3},[%4];"
        : "=r"(r0), "=r"(r1), "=r"(r2), "=r"(r3) : "r"(addr));
}

__device__ __forceinline__ void hmma16816(float* c, const uint32_t* a, const uint32_t* b) {
    asm volatile("mma.sync.aligned.m16n8k16.row.col.f32.f16.f16.f32 "
        "{%0,%1,%2,%3},{%4,%5,%6,%7},{%8,%9},{%0,%1,%2,%3};"
        : "+f"(c[0]), "+f"(c[1]), "+f"(c[2]), "+f"(c[3])
        : "r"(a[0]), "r"(a[1]), "r"(a[2]), "r"(a[3]), "r"(b[0]), "r"(b[1]));
}

__device__ __forceinline__ float act_apply(float v, int ACT) {
    if (ACT == 1) return v > 0.f ? v : 0.f;
    return __fdividef(1.f, 1.f + __expf(-v));   // ACT==2 fast sigmoid
}

// W[K][N] -> planes [2][N][K] (transpose + 2-split fp16)
__global__ void split_wt_kernel(const float* __restrict__ W,
                                __half* __restrict__ o, int K, int N) {
    int idx = blockIdx.x * blockDim.x + threadIdx.x;
    if (idx >= K * N) return;
    int k = idx / N, n = idx % N;
    __half h, m;
    split2(W[idx], h, m);
    size_t pl = (size_t)K * N;
    size_t off = (size_t)n * K + k;
    o[off] = h; o[pl + off] = m;
}

// ---------------- HMMA 2-split GEMM (2 CTAs/SM) ------------------------------
// A: fp32 [M][K]. B: 2 fp16 planes [2][ldN][K] (=W^T). Out: fp32 act [M][ldN].
// Products hh, hm, mh (mm dropped ~2^-24). CTA tile 128 x BN.
// A path: LDG -> regs -> split2 -> STS (no smem fp32 stage).
#define TROW 80                            // 64B data + 16B pad
#define TILE_A_B (128 * TROW)              // 10240 per A plane
#define APL_B (2 * TILE_A_B)               // 20480

template<int BN, int ACT>
__global__ void __launch_bounds__(256, 2)
hmma_gemm(const float* __restrict__ Af, const __half* __restrict__ Bp,
          const float* __restrict__ bias, float* __restrict__ Cout,
          int K, int ldN)
{
    constexpr int TILE_BB = BN * TROW;
    constexpr int BPL = 2 * TILE_BB;
    constexpr int BUF = APL_B + BPL;
    constexpr int NF = BN / 32;                // n-fragments per warp
    constexpr int NB_IT = BN / 32;             // B 16B-chunks per thread

    extern __shared__ char smem[];
    __shared__ float sbias[BN];
    const uint32_t sb = (uint32_t)__cvta_generic_to_shared(smem);
    const int tid = threadIdx.x, wid = tid >> 5, lane = tid & 31;
    const int brow = blockIdx.y * 128, bcol = blockIdx.x * BN;
    const int mbase = (wid >> 2) * 64;
    const int nbase = (wid & 3) * (BN / 4);
    const size_t bplane = (size_t)ldN * K;
    const int NT = K / 32;

    if (tid < BN) sbias[tid] = bias[bcol + tid];

    const char* Bg = (const char*)Bp;
    const int ar = tid >> 1;              // A row 0..127
    const int ah = (tid & 1) * 16;        // col offset 0/16
    const float* Aptr = Af + (size_t)(brow + ar) * K + ah;

    auto cp_b = [&](int kt, int b) {
        char* st = smem + b * BUF;
#pragma unroll
        for (int i = 0; i < NB_IT; i++) {
            int c = tid + i * 256;
            int p = c / (BN * 4), rem = c % (BN * 4);
            int row = rem >> 2, col4 = rem & 3;
            cp_async16(st + APL_B + p * TILE_BB + row * TROW + col4 * 16,
                Bg + ((size_t)p * bplane + (size_t)(bcol + row) * K) * 2
                   + (size_t)kt * 64 + col4 * 16);
        }
    };

    float4 areg[4];
    auto ldg_a = [&](int kt) {
#pragma unroll
        for (int q = 0; q < 4; q++)
            areg[q] = *(const float4*)(Aptr + (size_t)kt * 32 + q * 4);
    };
    auto sts_a = [&](int b) {
        char* ap = smem + b * BUF;
        const uint32_t off = (uint32_t)ar * TROW + ah * 2;
        __half2 hv[8], mv[8];
#pragma unroll
        for (int q = 0; q < 4; q++) {
            float vv[4] = {areg[q].x, areg[q].y, areg[q].z, areg[q].w};
            __half h[4], mq[4];
#pragma unroll
            for (int e = 0; e < 4; e++) split2(vv[e], h[e], mq[e]);
            hv[q * 2]     = __halves2half2(h[0], h[1]);
            hv[q * 2 + 1] = __halves2half2(h[2], h[3]);
            mv[q * 2]     = __halves2half2(mq[0], mq[1]);
            mv[q * 2 + 1] = __halves2half2(mq[2], mq[3]);
        }
        *(uint4*)(ap + off)                 = *(uint4*)&hv[0];
        *(uint4*)(ap + off + 16)            = *(uint4*)&hv[4];
        *(uint4*)(ap + TILE_A_B + off)      = *(uint4*)&mv[0];
        *(uint4*)(ap + TILE_A_B + off + 16) = *(uint4*)&mv[4];
    };

    float acc[4][NF][4];
#pragma unroll
    for (int i = 0; i < 4; i++)
#pragma unroll
        for (int j = 0; j < NF; j++)
#pragma unroll
            for (int q = 0; q < 4; q++) acc[i][j][q] = 0.f;

    // prologue: tile 0 fully staged, tile 1 in flight
    ldg_a(0); cp_b(0, 0); CP_COMMIT();
    sts_a(0);                       // stalls once on LDG(0)
    ldg_a(1); cp_b(1, 1); CP_COMMIT();
    asm volatile("cp.async.wait_group 1;");    // B(0) landed

    const int a_r  = (lane & 15);
    const int a_kc = (lane & 16) ? 16 : 0;
    const int b_n  = (lane & 7) + ((lane & 16) ? 8 : 0);
    const int b_kc = (lane & 8) ? 16 : 0;

    for (int kt = 0; kt < NT; kt++) {
        const int b = kt & 1;
        __syncthreads();                 // B1: buf b ready (B landed, A STS'd)
        const uint32_t stb = sb + b * BUF;
#pragma unroll
        for (int k16 = 0; k16 < 2; k16++) {
            const int kk = k16 * 32;
            uint32_t afr[4][4], bfr[NF][2];
#pragma unroll
            for (int pa = 0; pa < 2; pa++) {
                const uint32_t abase = stb + pa * TILE_A_B + kk + a_kc;
#pragma unroll
                for (int mf = 0; mf < 4; mf++)
                    ldsm_x4(afr[mf][0], afr[mf][1], afr[mf][2], afr[mf][3],
                            abase + (mbase + mf * 16 + a_r) * TROW);
                const int npb = 2 - pa;      // hh,hm then mh
#pragma unroll
                for (int pb = 0; pb < 2; pb++) {
                    if (pb >= npb) break;
                    const uint32_t bbase = stb + APL_B + pb * TILE_BB + kk + b_kc;
#pragma unroll
                    for (int nf2 = 0; nf2 < NF / 2; nf2++) {
                        uint32_t r0, r1, r2, r3;
                        ldsm_x4(r0, r1, r2, r3,
                                bbase + (nbase + nf2 * 16 + b_n) * TROW);
                        bfr[nf2 * 2 + 0][0] = r0; bfr[nf2 * 2 + 0][1] = r1;
                        bfr[nf2 * 2 + 1][0] = r2; bfr[nf2 * 2 + 1][1] = r3;
                    }
#pragma unroll
                    for (int mf = 0; mf < 4; mf++)
#pragma unroll
                        for (int nf = 0; nf < NF; nf++)
                            hmma16816(acc[mf][nf], afr[mf], bfr[nf]);
                }
            }
        }
        __syncthreads();                 // B2: all warps done reading buf b
        if (kt + 1 < NT) sts_a(b ^ 1);   // A(kt+1) halves -> buf b^1
        if (kt + 2 < NT) {
            ldg_a(kt + 2);               // raw A(kt+2) -> areg
            cp_b(kt + 2, b); CP_COMMIT();
        }
        if (kt + 1 < NT) {
            if (kt + 2 < NT) asm volatile("cp.async.wait_group 1;");
            else             asm volatile("cp.async.wait_group 0;");
        }
    }

    // ---- epilogue: bias + act -> fp32 ----
    const int qr = lane >> 2, qc = (lane & 3) * 2;
#pragma unroll
    for (int mf = 0; mf < 4; mf++) {
#pragma unroll
        for (int half = 0; half < 2; half++) {
            const int row = brow + mbase + mf * 16 + qr + half * 8;
#pragma unroll
            for (int nf = 0; nf < NF; nf++) {
                const int colL = nbase + nf * 8 + qc;
                float v0 = act_apply(acc[mf][nf][half * 2 + 0] + sbias[colL],     ACT);
                float v1 = act_apply(acc[mf][nf][half * 2 + 1] + sbias[colL + 1], ACT);
                *(float2*)(Cout + (size_t)row * ldN + bcol + colL) = make_float2(v0, v1);
            }
        }
    }
}

#define HS128 (2 * (APL_B + 2 * (128 * TROW)))   // 81920
#define HS64  (2 * (APL_B + 2 * ( 64 * TROW)))   // 61440

// d[r] = d2[r,:] . D3 + db3   (K = 64)
__global__ void dot_kernel(const float* __restrict__ d2, const float* __restrict__ D3,
                           const float* __restrict__ db3, float* __restrict__ dd)
{
    int gw   = (blockIdx.x * blockDim.x + threadIdx.x) >> 5;
    int lane = threadIdx.x & 31;
    if (gw >= MR) return;
    const float* row = d2 + (size_t)gw * 64;
    float s = row[lane] * D3[lane] + row[lane + 32] * D3[lane + 32];
#pragma unroll
    for (int o = 16; o > 0; o >>= 1) s += __shfl_down_sync(0xffffffffu, s, o);
    if (lane == 0) dd[gw] = s + db3[0];
}

// Per-bag: gumbel softmax, top-20 keep (stable), re-softmax, aggregate, project.
__global__ void __launch_bounds__(128)
final_kernel(const float* __restrict__ dd, const float* __restrict__ m,
             const float* __restrict__ u, const float* __restrict__ h3,
             const float* __restrict__ E, const float* __restrict__ eb,
             float* __restrict__ out_w, float* __restrict__ out_s)
{
    const int bag = blockIdx.x;
    const int t   = threadIdx.x;

    __shared__ float sm[64];
    __shared__ float wf[64];
    __shared__ float red[128];

    float z = 0.f;
    if (t < 64) {
        float logit = m[bag * 64 + t] * dd[bag * 64 + t];
        float uu = u[bag * 64 + t];
        float g = -logf(-logf(uu));
        z = (logit + g) / TAU_F;
    }

    red[t] = (t < 64) ? z : -INFINITY;
    __syncthreads();
#pragma unroll
    for (int s = 64; s >= 1; s >>= 1) {
        if (t < s) red[t] = fmaxf(red[t], red[t + s]);
        __syncthreads();
    }
    float zmax = red[0];
    __syncthreads();

    float e = (t < 64) ? expf(z - zmax) : 0.f;
    red[t] = e;
    __syncthreads();
#pragma unroll
    for (int s = 64; s >= 1; s >>= 1) {
        if (t < s) red[t] += red[t + s];
        __syncthreads();
    }
    float psum = red[0];
    __syncthreads();

    float p = e / psum;
    if (t < 64) sm[t] = p;
    __syncthreads();

    int keep = 0;
    if (t < 64) {
        int pos = 0;
#pragma unroll 8
        for (int j = 0; j < 64; j++) {
            float o = sm[j];
            pos += (o < p) || (o == p && j < t);
        }
        keep = (pos >= 44);
    }

    red[t] = (t < 64 && keep) ? p : -INFINITY;
    __syncthreads();
#pragma unroll
    for (int s = 64; s >= 1; s >>= 1) {
        if (t < s) red[t] = fmaxf(red[t], red[t + s]);
        __syncthreads();
    }
    float m2 = red[0];
    __syncthreads();

    float e2 = (t < 64 && keep) ? expf(p - m2) : 0.f;
    red[t] = e2;
    __syncthreads();
#pragma unroll
    for (int s = 64; s >= 1; s >>= 1) {
        if (t < s) red[t] += red[t + s];
        __syncthreads();
    }
    float s2 = red[0];
    __syncthreads();

    float wfin = (t < 64 && keep) ? (e2 / s2) : 0.f;
    if (t < 64) {
        wf[t] = wfin;
        out_w[bag * 64 + t] = wfin;
    }
    __syncthreads();

    const float* hb = h3 + (size_t)bag * 64 * 128;
    float agg = 0.f;
#pragma unroll 8
    for (int c = 0; c < 64; c++) agg += wf[c] * hb[c * 128 + t];
    red[t] = agg * E[t];
    __syncthreads();
#pragma unroll
    for (int s = 64; s >= 1; s >>= 1) {
        if (t < s) red[t] += red[t + s];
        __syncthreads();
    }
    if (t == 0) out_s[bag] = red[0] + eb[0];
}

// ---------------- launch ------------------------------------------------------
extern "C" void kernel_launch(void* const* d_in, const int* in_sizes, int n_in,
                              void* d_out, int out_size)
{
    const float* x   = (const float*)d_in[0];
    const float* m   = (const float*)d_in[1];
    const float* u   = (const float*)d_in[2];
    const float* W1  = (const float*)d_in[3];
    const float* b1  = (const float*)d_in[4];
    const float* W2  = (const float*)d_in[5];
    const float* b2  = (const float*)d_in[6];
    const float* W3  = (const float*)d_in[7];
    const float* b3  = (const float*)d_in[8];
    const float* D1  = (const float*)d_in[9];
    const float* db1 = (const float*)d_in[10];
    const float* D2  = (const float*)d_in[11];
    const float* db2 = (const float*)d_in[12];
    const float* D3  = (const float*)d_in[13];
    const float* db3 = (const float*)d_in[14];
    const float* E   = (const float*)d_in[15];
    const float* eb  = (const float*)d_in[16];
    float* out = (float*)d_out;

    __half *w1t, *w2t, *w3t, *dw1t, *dw2t;
    float *h1f, *h2f, *h3, *d1, *d2, *dd;
    cudaGetSymbolAddress((void**)&w1t,  g_w1t);
    cudaGetSymbolAddress((void**)&w2t,  g_w2t);
    cudaGetSymbolAddress((void**)&w3t,  g_w3t);
    cudaGetSymbolAddress((void**)&dw1t, g_dw1t);
    cudaGetSymbolAddress((void**)&dw2t, g_dw2t);
    cudaGetSymbolAddress((void**)&h1f,  g_h1f);
    cudaGetSymbolAddress((void**)&h2f,  g_h2f);
    cudaGetSymbolAddress((void**)&h3,   g_h3);
    cudaGetSymbolAddress((void**)&d1,   g_d1);
    cudaGetSymbolAddress((void**)&d2,   g_d2);
    cudaGetSymbolAddress((void**)&dd,   g_dd);

    static int attr_done = 0;
    if (!attr_done) {
        cudaFuncSetAttribute(hmma_gemm<128,1>, cudaFuncAttributeMaxDynamicSharedMemorySize, HS128);
        cudaFuncSetAttribute(hmma_gemm<128,2>, cudaFuncAttributeMaxDynamicSharedMemorySize, HS128);
        cudaFuncSetAttribute(hmma_gemm< 64,2>, cudaFuncAttributeMaxDynamicSharedMemorySize, HS64);
        attr_done = 1;
    }

    // weight splits (tiny)
    split_wt_kernel<<<(512 * 256 + 255) / 256, 256>>>(W1, w1t, 512, 256);
    split_wt_kernel<<<(256 * 256 + 255) / 256, 256>>>(W2, w2t, 256, 256);
    split_wt_kernel<<<(256 * 128 + 255) / 256, 256>>>(W3, w3t, 256, 128);
    split_wt_kernel<<<(128 * 128 + 255) / 256, 256>>>(D1, dw1t, 128, 128);
    split_wt_kernel<<<(128 *  64 + 255) / 256, 256>>>(D2, dw2t, 128, 64);

    // all dense layers on HMMA (fp16 2-split/3-product), 2 CTAs/SM
    hmma_gemm<128,1><<<dim3(2, MR / 128), 256, HS128>>>(x,   w1t,  b1,  h1f, 512, 256);
    hmma_gemm<128,1><<<dim3(2, MR / 128), 256, HS128>>>(h1f, w2t,  b2,  h2f, 256, 256);
    hmma_gemm<128,1><<<dim3(1, MR / 128), 256, HS128>>>(h2f, w3t,  b3,  h3,  256, 128);
    hmma_gemm<128,2><<<dim3(1, MR / 128), 256, HS128>>>(h3,  dw1t, db1, d1,  128, 128);
    hmma_gemm< 64,2><<<dim3(1, MR / 128), 256, HS64 >>>(d1,  dw2t, db2, d2,  128, 64);

    // tail
    dot_kernel<<<MR / 8, 256>>>(d2, D3, db3, dd);
    final_kernel<<<NB, 128>>>(dd, m, u, h3, E, eb, out, out + MR);
}